// round 6
// baseline (speedup 1.0000x reference)
#include <cuda_runtime.h>
#include <math.h>

#define Lq 256
#define Dm 300
#define Sm 16
#define SK 16
#define Em 2048
#define Cm 7
#define NEGV -1000000000.0f

// ---------------- scratch (device globals; no allocation) ----------------
__device__ float g_Lin[Lq * 1800];       // [P0 | P1 | Hself | Q | K | V] per row
__device__ float g_hidden[Lq * Dm];
__device__ float g_ctx[Lq * Dm];
__device__ float g_relatt[Lq * Dm];
__device__ float g_nodes[Lq * 48 * Dm];  // 14.7 MB
__device__ float g_score[Lq * 48];
__device__ int   g_nmask[Lq * 48];
__device__ float g_fuse[Lq * Dm];
__device__ float g_sym[Lq * Dm];

struct BPtrs { const float* p[6]; };

__device__ __forceinline__ float warp_sum(float v) {
#pragma unroll
    for (int o = 16; o; o >>= 1) v += __shfl_xor_sync(0xffffffffu, v, o);
    return v;
}
__device__ __forceinline__ float warp_max(float v) {
#pragma unroll
    for (int o = 16; o; o >>= 1) v = fmaxf(v, __shfl_xor_sync(0xffffffffu, v, o));
    return v;
}

// ---------------- generic tiled SGEMM ----------------
// AMODE 0: A is the passed pointer, row-major M x Kd
// AMODE 1: A row l is the concat [g_hidden[l] | g_relatt[l] | g_sym[l]] (Kd = 900)
// BMODE 0: B = B.p[0], row-major Kd x N (ldb = N)
// BMODE 1: six concatenated 300x300 matrices: N = 1800, col c -> matrix c/300
template <int AMODE, int BMODE>
__global__ void sgemm_kernel(const float* __restrict__ A, BPtrs B, float* __restrict__ C,
                             int M, int N, int Kd, const float* __restrict__ bias, int relu)
{
    const int BM = 64, BN = 64, BK = 16;
    __shared__ float As[BK][BM];
    __shared__ float Bs[BK][BN];
    int tid = threadIdx.x;                 // 256 threads
    int tx = tid & 15, ty = tid >> 4;
    int rowBase = blockIdx.y * BM;
    int colBase = blockIdx.x * BN;
    float acc[4][4];
#pragma unroll
    for (int i = 0; i < 4; i++)
#pragma unroll
        for (int j = 0; j < 4; j++) acc[i][j] = 0.f;

    for (int k0 = 0; k0 < Kd; k0 += BK) {
#pragma unroll
        for (int i = tid; i < BM * BK; i += 256) {
            int r = i >> 4, kk = i & 15;
            int gr = rowBase + r, gk = k0 + kk;
            float v = 0.f;
            if (gr < M && gk < Kd) {
                if (AMODE == 1) {
                    if (gk < 300)      v = g_hidden[gr * 300 + gk];
                    else if (gk < 600) v = g_relatt[gr * 300 + gk - 300];
                    else               v = g_sym[gr * 300 + gk - 600];
                } else {
                    v = A[gr * Kd + gk];
                }
            }
            As[kk][r] = v;
        }
#pragma unroll
        for (int i = tid; i < BK * BN; i += 256) {
            int kk = i >> 6, c = i & 63;
            int gk = k0 + kk, gc = colBase + c;
            float v = 0.f;
            if (gk < Kd && gc < N) {
                if (BMODE == 1) { int m = gc / 300; int o = gc - m * 300; v = B.p[m][gk * 300 + o]; }
                else            { v = B.p[0][gk * N + gc]; }
            }
            Bs[kk][c] = v;
        }
        __syncthreads();
#pragma unroll
        for (int kk = 0; kk < BK; kk++) {
            float ra[4], rb[4];
#pragma unroll
            for (int i = 0; i < 4; i++) ra[i] = As[kk][ty * 4 + i];
#pragma unroll
            for (int j = 0; j < 4; j++) rb[j] = Bs[kk][tx * 4 + j];
#pragma unroll
            for (int i = 0; i < 4; i++)
#pragma unroll
                for (int j = 0; j < 4; j++) acc[i][j] += ra[i] * rb[j];
        }
        __syncthreads();
    }
#pragma unroll
    for (int i = 0; i < 4; i++) {
        int gr = rowBase + ty * 4 + i;
        if (gr >= M) continue;
#pragma unroll
        for (int j = 0; j < 4; j++) {
            int gc = colBase + tx * 4 + j;
            if (gc >= N) continue;
            float v = acc[i][j];
            if (bias) v += bias[gc];
            if (relu) v = fmaxf(v, 0.f);
            C[gr * N + gc] = v;
        }
    }
}

// ---------------- RGCN: hidden[l] = Hself[l] + b + sum_{e: dst==l} c0*P0[src]+c1*P1[src] ----------------
__global__ void k_rgcn(const float* __restrict__ b_rgcn,
                       const int* __restrict__ esrc, const int* __restrict__ edst,
                       const int* __restrict__ etyp, const float* __restrict__ comp)
{
    int l = blockIdx.x;
    int tid = threadIdx.x;  // 128
    __shared__ int sdst[Em];
    for (int i = tid; i < Em; i += 128) sdst[i] = edst[i];
    int d0 = tid, d1 = tid + 128, d2 = tid + 256;
    float acc0 = g_Lin[l * 1800 + 600 + d0] + b_rgcn[d0];
    float acc1 = (d1 < Dm) ? g_Lin[l * 1800 + 600 + d1] + b_rgcn[d1] : 0.f;
    float acc2 = (d2 < Dm) ? g_Lin[l * 1800 + 600 + d2] + b_rgcn[d2] : 0.f;
    __syncthreads();
    for (int e = 0; e < Em; e++) {
        if (sdst[e] == l) {
            int s = esrc[e]; int t = etyp[e];
            float c0 = comp[2 * t], c1 = comp[2 * t + 1];
            const float* p0 = g_Lin + s * 1800;
            const float* p1 = p0 + 300;
            acc0 += c0 * p0[d0] + c1 * p1[d0];
            if (d1 < Dm) acc1 += c0 * p0[d1] + c1 * p1[d1];
            if (d2 < Dm) acc2 += c0 * p0[d2] + c1 * p1[d2];
        }
    }
    g_hidden[l * Dm + d0] = acc0;
    if (d1 < Dm) g_hidden[l * Dm + d1] = acc1;
    if (d2 < Dm) g_hidden[l * Dm + d2] = acc2;
}

// ---------------- windowed attention (middle query only) -> ctx ----------------
__global__ void k_relatt_ctx()
{
    int l = blockIdx.x;
    int tid = threadIdx.x;            // 256
    int w = tid >> 5, lane = tid & 31;
    __shared__ float ssc[2][3];
    __shared__ float sat[2][3];
    int w0 = max(l - 1, 0), w1 = l, w2 = min(l + 1, Lq - 1);
    int wins[3] = {w0, w1, w2};
    if (w < 6) {
        int h = w / 3, j = w - h * 3;
        const float* q  = g_Lin + l * 1800 + 900 + h * 150;
        const float* kk = g_Lin + wins[j] * 1800 + 1200 + h * 150;
        float a = 0.f;
        for (int d = lane; d < 150; d += 32) a += q[d] * kk[d];
        a = warp_sum(a);
        if (lane == 0) ssc[h][j] = a * (1.0f / sqrtf(150.0f));
    }
    __syncthreads();
    if (tid < 2) {
        int h = tid;
        float m = fmaxf(ssc[h][0], fmaxf(ssc[h][1], ssc[h][2]));
        float e0 = __expf(ssc[h][0] - m), e1 = __expf(ssc[h][1] - m), e2 = __expf(ssc[h][2] - m);
        float inv = 1.0f / (e0 + e1 + e2);
        sat[h][0] = e0 * inv; sat[h][1] = e1 * inv; sat[h][2] = e2 * inv;
    }
    __syncthreads();
    for (int d = tid; d < Dm; d += blockDim.x) {
        int h = d / 150;
        float v = sat[h][0] * g_Lin[w0 * 1800 + 1500 + d]
                + sat[h][1] * g_Lin[w1 * 1800 + 1500 + d]
                + sat[h][2] * g_Lin[w2 * 1800 + 1500 + d];
        g_ctx[l * Dm + d] = v;
    }
}

// ---------------- concept-graph node builder: one block per (b,l,s) ----------------
__global__ void k_nodes(const float* __restrict__ table,
                        const int* __restrict__ src_ids, const int* __restrict__ dst_ids,
                        const float* __restrict__ wgt, const float* __restrict__ sentic,
                        const float* __restrict__ rvecs)
{
    int idx = blockIdx.x;
    int s = idx & 15;
    int l = (idx >> 4) & 255;
    int b = idx >> 12;
    int n = b * Sm + s;
    int tid = threadIdx.x;            // 128
    int w = tid >> 5, lane = tid & 31;

    __shared__ float sm_rel[Dm], sm_src[Dm], sm_rv[Dm], sm_sr[Dm];
    __shared__ float sm_dst[SK][Dm];
    __shared__ float sm_d1[SK], sm_nr[SK], sm_d2[SK], sm_coef[SK];
    __shared__ int sm_id[SK];
    __shared__ float sm_red[4];
    __shared__ float sm_rn;

    int sid = src_ids[(b * Lq + l) * Sm + s];
    int nrow = (l * 48 + n) * Dm;
    if (sid < 0) {
        if (tid == 0) { g_score[l * 48 + n] = NEGV; g_nmask[l * 48 + n] = 0; }
        for (int d = tid; d < Dm; d += 128) g_nodes[nrow + d] = 0.f;
        return;
    }
    if (tid < SK) sm_id[tid] = dst_ids[((b * Lq + l) * Sm + s) * SK + tid];

    float pn = 0.f;
    // rows are 300 floats = 1200 B -> 16B-aligned float4 loads (75 per row)
    {
        const float4* relr = (const float4*)(g_relatt + l * Dm);
        const float4* srcr = (const float4*)(table + (long)sid * Dm);
        const float4* rvr  = (const float4*)(rvecs + b * Dm);
        for (int i = tid; i < 75; i += 128) {
            float4 rr = relr[i];
            float4 sv = srcr[i];
            float4 rv = rvr[i];
            ((float4*)sm_rel)[i] = rr;
            ((float4*)sm_src)[i] = sv;
            ((float4*)sm_rv)[i]  = rv;
            float4 sr; sr.x = sv.x * rv.x; sr.y = sv.y * rv.y; sr.z = sv.z * rv.z; sr.w = sv.w * rv.w;
            ((float4*)sm_sr)[i] = sr;
            pn += rr.x * rr.x + rr.y * rr.y + rr.z * rr.z + rr.w * rr.w;
        }
    }
    pn = warp_sum(pn);
    if (lane == 0) sm_red[w] = pn;
    __syncthreads();
    if (tid == 0) sm_rn = sqrtf(sm_red[0] + sm_red[1] + sm_red[2] + sm_red[3]);
    __syncthreads();

    // gather 16 dst rows, float4-flattened: 16 * 75 = 1200 float4 elements
    for (int i = tid; i < SK * 75; i += 128) {
        int k = i / 75, d4 = i - k * 75;
        int id = sm_id[k];
        float4 v;
        if (id >= 0) v = ((const float4*)(table + (long)id * Dm))[d4];
        else         { v.x = v.y = v.z = v.w = 0.f; }
        ((float4*)(&sm_dst[k][0]))[d4] = v;
    }
    __syncthreads();

    for (int k = w; k < SK; k += 4) {
        float a1 = 0.f, a2 = 0.f, a3 = 0.f;
        for (int d = lane; d < Dm; d += 32) {
            float x = sm_dst[k][d];
            a1 += sm_rel[d] * x;
            a2 += x * x;
            a3 += sm_sr[d] * x;
        }
        a1 = warp_sum(a1); a2 = warp_sum(a2); a3 = warp_sum(a3);
        if (lane == 0) { sm_d1[k] = a1; sm_nr[k] = a2; sm_d2[k] = a3; }
    }
    __syncthreads();

    if (tid < 32) {
        int k = lane;
        bool valid = (k < SK) && (sm_id[k] >= 0);
        float omega = -INFINITY;
        if (valid) {
            long base = ((long)(b * Lq + l) * Sm + s) * SK + k;
            float cosv = fabsf(sm_d1[k]) / (sm_rn * sqrtf(sm_nr[k]) + 1e-8f);
            omega = 0.5f * wgt[base] * cosv + 0.5f * fabsf(sentic[base]);
        }
        float m = warp_max(omega);
        float e = valid ? __expf(omega - m) : 0.f;
        float ssum = warp_sum(e);
        float alpha1 = (ssum > 0.f) ? e / ssum : 0.f;
        float sv = valid ? alpha1 * sm_d2[k] : -INFINITY;
        float m2 = warp_max(sv);
        float e2 = valid ? __expf(sv - m2) : 0.f;
        float ssum2 = warp_sum(e2);
        float alpha2 = (ssum2 > 0.f) ? e2 / ssum2 : 0.f;
        if (k < SK) sm_coef[k] = alpha1 * alpha2;
    }
    __syncthreads();

    float psc = 0.f;
    for (int d = tid; d < Dm; d += 128) {
        float a = 0.f;
#pragma unroll
        for (int k = 0; k < SK; k++) a += sm_coef[k] * sm_dst[k][d];
        float nd = sm_src[d] + sm_rv[d] * a;
        g_nodes[nrow + d] = nd;
        psc += nd * sm_rel[d];
    }
    psc = warp_sum(psc);
    if (lane == 0) sm_red[w] = psc;
    __syncthreads();
    if (tid == 0) { g_score[l * 48 + n] = sm_red[0] + sm_red[1] + sm_red[2] + sm_red[3]; g_nmask[l * 48 + n] = 1; }
}

// ---------------- node-level attention -> sym ----------------
__global__ void k_sym()
{
    int l = blockIdx.x;
    int tid = threadIdx.x;  // 256
    __shared__ float att[48];
    __shared__ int sany;
    if (tid == 0) {
        float m = -INFINITY; int any = 0;
        for (int nn = 0; nn < 48; nn++)
            if (g_nmask[l * 48 + nn]) { any = 1; m = fmaxf(m, g_score[l * 48 + nn]); }
        float ssum = 0.f;
        for (int nn = 0; nn < 48; nn++) {
            float e = g_nmask[l * 48 + nn] ? __expf(g_score[l * 48 + nn] - m) : 0.f;
            att[nn] = e; ssum += e;
        }
        float inv = (ssum > 0.f) ? 1.f / ssum : 0.f;
        for (int nn = 0; nn < 48; nn++) att[nn] *= inv;
        sany = any;
    }
    __syncthreads();
    for (int d = tid; d < Dm; d += 256) {
        float a = 0.f;
        for (int nn = 0; nn < 48; nn++) a += att[nn] * g_nodes[(l * 48 + nn) * Dm + d];
        g_sym[l * Dm + d] = sany ? a : 0.f;
    }
}

// ---------------- final projection + log_softmax ----------------
__global__ void k_out(const float* __restrict__ Wout,
                      const float* __restrict__ bout, float* __restrict__ out)
{
    int l = blockIdx.x;
    int tid = threadIdx.x;  // 256
    int w = tid >> 5, lane = tid & 31;
    __shared__ float hs[Dm];
    __shared__ float logits[8];
    __shared__ float lse;
    for (int d = tid; d < Dm; d += 256) hs[d] = g_fuse[l * Dm + d];
    __syncthreads();
    if (w < Cm) {
        float a = 0.f;
        for (int d = lane; d < Dm; d += 32) a += hs[d] * Wout[d * Cm + w];
        a = warp_sum(a);
        if (lane == 0) logits[w] = a + bout[w];
    }
    __syncthreads();
    if (tid == 0) {
        float m = logits[0];
        for (int c = 1; c < Cm; c++) m = fmaxf(m, logits[c]);
        float ssum = 0.f;
        for (int c = 0; c < Cm; c++) ssum += __expf(logits[c] - m);
        lse = m + logf(ssum);
    }
    __syncthreads();
    if (tid < Cm) out[l * Cm + tid] = logits[tid] - lse;
}

// ---------------- launch ----------------
extern "C" void kernel_launch(void* const* d_in, const int* in_sizes, int n_in,
                              void* d_out, int out_size)
{
    (void)in_sizes; (void)n_in; (void)out_size;
    const float* utt   = (const float*)d_in[0];
    const int*   esrc  = (const int*)d_in[1];
    const int*   edst  = (const int*)d_in[2];
    const int*   etyp  = (const int*)d_in[3];
    const int*   csrc  = (const int*)d_in[4];
    const int*   cdst  = (const int*)d_in[5];
    const float* cwgt  = (const float*)d_in[6];
    const float* csen  = (const float*)d_in[7];
    const float* table = (const float*)d_in[8];
    const float* Wb    = (const float*)d_in[9];
    const float* comp  = (const float*)d_in[10];
    const float* Wself = (const float*)d_in[11];
    const float* brg   = (const float*)d_in[12];
    const float* Wq    = (const float*)d_in[13];
    const float* Wk    = (const float*)d_in[14];
    const float* Wv    = (const float*)d_in[15];
    const float* Wo    = (const float*)d_in[16];
    const float* rvec  = (const float*)d_in[17];
    const float* Wfuse = (const float*)d_in[18];
    const float* bfuse = (const float*)d_in[19];
    const float* Wout  = (const float*)d_in[20];
    const float* bout  = (const float*)d_in[21];

    // device-global scratch addresses are resolved inside the kernels;
    // kernel_launch itself is pure kernel launches (graph-capture safe).

    // 1) six fused linears: [P0|P1|Hself|Q|K|V] = utt @ [Wb0|Wb1|Wself|Wq|Wk|Wv]
    BPtrs six; six.p[0] = Wb; six.p[1] = Wb + 300 * 300; six.p[2] = Wself;
    six.p[3] = Wq; six.p[4] = Wk; six.p[5] = Wv;
    {
        float* pLin;
        // g_Lin is written through C pointer inside sgemm; get its address via a kernel-visible trick:
        // sgemm writes through C param, so pass the global's device address using the
        // fact that device globals can be referenced from host only via symbol APIs —
        // instead, route C through a dedicated global-writing path: use AMODE/BMODE kernels
        // that write to fixed globals would add variants; simplest legal path: one tiny
        // cudaMemcpyAsync-free approach — pass nullptr and have the kernel detect?
        // We instead instantiate sgemm with explicit C pointers fetched ONCE below.
        pLin = nullptr; (void)pLin;
    }
    // Fetch global addresses via cudaGetSymbolAddress is a pure host-side lookup
    // (no stream op, no allocation) and is capture-safe; used only for GEMM C/A ptrs.
    static float* pLin = nullptr; static float* pCtx = nullptr; static float* pRel = nullptr; static float* pFuse = nullptr;
    if (!pLin) {
        cudaGetSymbolAddress((void**)&pLin,  g_Lin);
        cudaGetSymbolAddress((void**)&pCtx,  g_ctx);
        cudaGetSymbolAddress((void**)&pRel,  g_relatt);
        cudaGetSymbolAddress((void**)&pFuse, g_fuse);
    }

    sgemm_kernel<0, 1><<<dim3(29, 4), 256>>>(utt, six, pLin, Lq, 1800, Dm, nullptr, 0);

    // 2) RGCN (deterministic per-dst edge scan)
    k_rgcn<<<Lq, 128>>>(brg, esrc, edst, etyp, comp);

    // 3) windowed attention context, then @ Wo
    k_relatt_ctx<<<Lq, 256>>>();
    BPtrs bo; bo.p[0] = Wo; bo.p[1] = bo.p[2] = bo.p[3] = bo.p[4] = bo.p[5] = nullptr;
    sgemm_kernel<0, 0><<<dim3(5, 4), 256>>>(pCtx, bo, pRel, Lq, Dm, Dm, nullptr, 0);

    // 4) concept-graph nodes (the gather-heavy kernel)
    k_nodes<<<3 * Lq * Sm, 128>>>(table, csrc, cdst, cwgt, csen, rvec);

    // 5) node attention -> sym
    k_sym<<<Lq, 256>>>();

    // 6) fused [hidden|relatt|sym] @ Wfuse (+bias+relu), then head + log_softmax
    BPtrs bf; bf.p[0] = Wfuse; bf.p[1] = bf.p[2] = bf.p[3] = bf.p[4] = bf.p[5] = nullptr;
    sgemm_kernel<1, 0><<<dim3(5, 4), 256>>>(nullptr, bf, pFuse, Lq, Dm, 900, bfuse, 1);
    k_out<<<Lq, 256>>>(Wout, bout, (float*)d_out);
}

// round 11
// speedup vs baseline: 2.1138x; 2.1138x over previous
#include <cuda_runtime.h>
#include <math.h>

#define Lq 256
#define Dm 300
#define Sm 16
#define SK 16
#define Em 2048
#define Cm 7
#define NEGV -1000000000.0f

// ---------------- scratch (device globals; no allocation) ----------------
__device__ float g_Lin[Lq * 1800];       // [P0 | P1 | Hself | Q | K | V] per row
__device__ float g_hidden[Lq * Dm];
__device__ float g_ctx[Lq * Dm];
__device__ float g_relatt[Lq * Dm];
__device__ float g_nodes[Lq * 48 * Dm];  // 14.7 MB
__device__ float g_score[Lq * 48];
__device__ int   g_nmask[Lq * 48];
__device__ float g_fuse[Lq * Dm];
__device__ float g_sym[Lq * Dm];
__device__ float g_part[2 * Lq * 1800];  // split-K partials (max: Lin KS=2), 3.7 MB

struct BPtrs { const float* p[6]; };

__device__ __forceinline__ float warp_sum(float v) {
#pragma unroll
    for (int o = 16; o; o >>= 1) v += __shfl_xor_sync(0xffffffffu, v, o);
    return v;
}
__device__ __forceinline__ float warp_max(float v) {
#pragma unroll
    for (int o = 16; o; o >>= 1) v = fmaxf(v, __shfl_xor_sync(0xffffffffu, v, o));
    return v;
}

// ---------------- split-K tiled SGEMM ----------------
// AMODE 0: A is the passed pointer, row-major M x Kd
// AMODE 1: A row l is the concat [g_hidden[l] | g_relatt[l] | g_sym[l]] (Kd = 900)
// BMODE 0: B = B.p[0], row-major Kd x N (ldb = N)
// BMODE 1: six concatenated 300x300 matrices: N = 1800, col c -> matrix c/300
// blockIdx.z = split-K slice; writes partial sums to Cpart[z * M*N + ...]
template <int AMODE, int BMODE>
__global__ __launch_bounds__(256)
void sgemm_splitk(const float* __restrict__ A, BPtrs B, float* __restrict__ Cpart,
                  int M, int N, int Kd, int kChunk)
{
    const int BM = 64, BN = 64, BK = 16;
    __shared__ float As[BK][BM];
    __shared__ float Bs[BK][BN];
    int tid = threadIdx.x;                 // 256 threads
    int tx = tid & 15, ty = tid >> 4;
    int rowBase = blockIdx.y * BM;
    int colBase = blockIdx.x * BN;
    int ks = blockIdx.z;
    int kBeg = ks * kChunk;
    int kEnd = min(Kd, kBeg + kChunk);
    float acc[4][4];
#pragma unroll
    for (int i = 0; i < 4; i++)
#pragma unroll
        for (int j = 0; j < 4; j++) acc[i][j] = 0.f;

    for (int k0 = kBeg; k0 < kEnd; k0 += BK) {
#pragma unroll
        for (int i = tid; i < BM * BK; i += 256) {
            int r = i >> 4, kk = i & 15;
            int gr = rowBase + r, gk = k0 + kk;
            float v = 0.f;
            if (gr < M && gk < kEnd) {
                if (AMODE == 1) {
                    if (gk < 300)      v = g_hidden[gr * 300 + gk];
                    else if (gk < 600) v = g_relatt[gr * 300 + gk - 300];
                    else               v = g_sym[gr * 300 + gk - 600];
                } else {
                    v = A[gr * Kd + gk];
                }
            }
            As[kk][r] = v;
        }
#pragma unroll
        for (int i = tid; i < BK * BN; i += 256) {
            int kk = i >> 6, c = i & 63;
            int gk = k0 + kk, gc = colBase + c;
            float v = 0.f;
            if (gk < kEnd && gc < N) {
                if (BMODE == 1) { int m = gc / 300; int o = gc - m * 300; v = B.p[m][gk * 300 + o]; }
                else            { v = B.p[0][gk * N + gc]; }
            }
            Bs[kk][c] = v;
        }
        __syncthreads();
#pragma unroll
        for (int kk = 0; kk < BK; kk++) {
            float ra[4], rb[4];
#pragma unroll
            for (int i = 0; i < 4; i++) ra[i] = As[kk][ty * 4 + i];
#pragma unroll
            for (int j = 0; j < 4; j++) rb[j] = Bs[kk][tx * 4 + j];
#pragma unroll
            for (int i = 0; i < 4; i++)
#pragma unroll
                for (int j = 0; j < 4; j++) acc[i][j] += ra[i] * rb[j];
        }
        __syncthreads();
    }
    float* Cp = Cpart + (size_t)ks * M * N;
#pragma unroll
    for (int i = 0; i < 4; i++) {
        int gr = rowBase + ty * 4 + i;
        if (gr >= M) continue;
#pragma unroll
        for (int j = 0; j < 4; j++) {
            int gc = colBase + tx * 4 + j;
            if (gc >= N) continue;
            Cp[gr * N + gc] = acc[i][j];
        }
    }
}

// ---------------- split-K reduction: out[i] = sum_ks part[ks][i] (+bias, relu) ----------------
// n4 = (M*N)/4. bias==nullptr -> plain sum. N divisible by 4.
__global__ __launch_bounds__(256)
void reduce_splitk(const float4* __restrict__ part, float4* __restrict__ out,
                   int n4, int KS, const float* __restrict__ bias, int relu, int N)
{
    int i = blockIdx.x * blockDim.x + threadIdx.x;
    if (i >= n4) return;
    float4 a = part[i];
    for (int ks = 1; ks < KS; ks++) {
        float4 b = part[(size_t)ks * n4 + i];
        a.x += b.x; a.y += b.y; a.z += b.z; a.w += b.w;
    }
    if (bias) {
        int c = (i * 4) % N;
        const float4 bv = *(const float4*)(bias + c);
        a.x += bv.x; a.y += bv.y; a.z += bv.z; a.w += bv.w;
    }
    if (relu) {
        a.x = fmaxf(a.x, 0.f); a.y = fmaxf(a.y, 0.f);
        a.z = fmaxf(a.z, 0.f); a.w = fmaxf(a.w, 0.f);
    }
    out[i] = a;
}

// ---------------- RGCN: hidden[l] = Hself[l] + b + sum_{e: dst==l} c0*P0[src]+c1*P1[src] ----------------
__global__ void k_rgcn(const float* __restrict__ b_rgcn,
                       const int* __restrict__ esrc, const int* __restrict__ edst,
                       const int* __restrict__ etyp, const float* __restrict__ comp)
{
    int l = blockIdx.x;
    int tid = threadIdx.x;  // 128
    __shared__ int sdst[Em];
    for (int i = tid; i < Em; i += 128) sdst[i] = edst[i];
    int d0 = tid, d1 = tid + 128, d2 = tid + 256;
    float acc0 = g_Lin[l * 1800 + 600 + d0] + b_rgcn[d0];
    float acc1 = (d1 < Dm) ? g_Lin[l * 1800 + 600 + d1] + b_rgcn[d1] : 0.f;
    float acc2 = (d2 < Dm) ? g_Lin[l * 1800 + 600 + d2] + b_rgcn[d2] : 0.f;
    __syncthreads();
    for (int e = 0; e < Em; e++) {
        if (sdst[e] == l) {
            int s = esrc[e]; int t = etyp[e];
            float c0 = comp[2 * t], c1 = comp[2 * t + 1];
            const float* p0 = g_Lin + s * 1800;
            const float* p1 = p0 + 300;
            acc0 += c0 * p0[d0] + c1 * p1[d0];
            if (d1 < Dm) acc1 += c0 * p0[d1] + c1 * p1[d1];
            if (d2 < Dm) acc2 += c0 * p0[d2] + c1 * p1[d2];
        }
    }
    g_hidden[l * Dm + d0] = acc0;
    if (d1 < Dm) g_hidden[l * Dm + d1] = acc1;
    if (d2 < Dm) g_hidden[l * Dm + d2] = acc2;
}

// ---------------- windowed attention (middle query only) -> ctx ----------------
__global__ void k_relatt_ctx()
{
    int l = blockIdx.x;
    int tid = threadIdx.x;            // 256
    int w = tid >> 5, lane = tid & 31;
    __shared__ float ssc[2][3];
    __shared__ float sat[2][3];
    int w0 = max(l - 1, 0), w1 = l, w2 = min(l + 1, Lq - 1);
    int wins[3] = {w0, w1, w2};
    if (w < 6) {
        int h = w / 3, j = w - h * 3;
        const float* q  = g_Lin + l * 1800 + 900 + h * 150;
        const float* kk = g_Lin + wins[j] * 1800 + 1200 + h * 150;
        float a = 0.f;
        for (int d = lane; d < 150; d += 32) a += q[d] * kk[d];
        a = warp_sum(a);
        if (lane == 0) ssc[h][j] = a * (1.0f / sqrtf(150.0f));
    }
    __syncthreads();
    if (tid < 2) {
        int h = tid;
        float m = fmaxf(ssc[h][0], fmaxf(ssc[h][1], ssc[h][2]));
        float e0 = __expf(ssc[h][0] - m), e1 = __expf(ssc[h][1] - m), e2 = __expf(ssc[h][2] - m);
        float inv = 1.0f / (e0 + e1 + e2);
        sat[h][0] = e0 * inv; sat[h][1] = e1 * inv; sat[h][2] = e2 * inv;
    }
    __syncthreads();
    for (int d = tid; d < Dm; d += blockDim.x) {
        int h = d / 150;
        float v = sat[h][0] * g_Lin[w0 * 1800 + 1500 + d]
                + sat[h][1] * g_Lin[w1 * 1800 + 1500 + d]
                + sat[h][2] * g_Lin[w2 * 1800 + 1500 + d];
        g_ctx[l * Dm + d] = v;
    }
}

// ---------------- concept-graph node builder: one block per (b,l,s) ----------------
__global__ void k_nodes(const float* __restrict__ table,
                        const int* __restrict__ src_ids, const int* __restrict__ dst_ids,
                        const float* __restrict__ wgt, const float* __restrict__ sentic,
                        const float* __restrict__ rvecs)
{
    int idx = blockIdx.x;
    int s = idx & 15;
    int l = (idx >> 4) & 255;
    int b = idx >> 12;
    int n = b * Sm + s;
    int tid = threadIdx.x;            // 128
    int w = tid >> 5, lane = tid & 31;

    __shared__ float sm_rel[Dm], sm_src[Dm], sm_rv[Dm], sm_sr[Dm];
    __shared__ float sm_dst[SK][Dm];
    __shared__ float sm_d1[SK], sm_nr[SK], sm_d2[SK], sm_coef[SK];
    __shared__ int sm_id[SK];
    __shared__ float sm_red[4];
    __shared__ float sm_rn;

    int sid = src_ids[(b * Lq + l) * Sm + s];
    int nrow = (l * 48 + n) * Dm;
    if (sid < 0) {
        if (tid == 0) { g_score[l * 48 + n] = NEGV; g_nmask[l * 48 + n] = 0; }
        for (int d = tid; d < Dm; d += 128) g_nodes[nrow + d] = 0.f;
        return;
    }
    if (tid < SK) sm_id[tid] = dst_ids[((b * Lq + l) * Sm + s) * SK + tid];

    float pn = 0.f;
    // rows are 300 floats = 1200 B -> 16B-aligned float4 loads (75 per row)
    {
        const float4* relr = (const float4*)(g_relatt + l * Dm);
        const float4* srcr = (const float4*)(table + (long)sid * Dm);
        const float4* rvr  = (const float4*)(rvecs + b * Dm);
        for (int i = tid; i < 75; i += 128) {
            float4 rr = relr[i];
            float4 sv = srcr[i];
            float4 rv = rvr[i];
            ((float4*)sm_rel)[i] = rr;
            ((float4*)sm_src)[i] = sv;
            ((float4*)sm_rv)[i]  = rv;
            float4 sr; sr.x = sv.x * rv.x; sr.y = sv.y * rv.y; sr.z = sv.z * rv.z; sr.w = sv.w * rv.w;
            ((float4*)sm_sr)[i] = sr;
            pn += rr.x * rr.x + rr.y * rr.y + rr.z * rr.z + rr.w * rr.w;
        }
    }
    pn = warp_sum(pn);
    if (lane == 0) sm_red[w] = pn;
    __syncthreads();
    if (tid == 0) sm_rn = sqrtf(sm_red[0] + sm_red[1] + sm_red[2] + sm_red[3]);
    __syncthreads();

    // gather 16 dst rows, float4-flattened: 16 * 75 = 1200 float4 elements
    for (int i = tid; i < SK * 75; i += 128) {
        int k = i / 75, d4 = i - k * 75;
        int id = sm_id[k];
        float4 v;
        if (id >= 0) v = ((const float4*)(table + (long)id * Dm))[d4];
        else         { v.x = v.y = v.z = v.w = 0.f; }
        ((float4*)(&sm_dst[k][0]))[d4] = v;
    }
    __syncthreads();

    for (int k = w; k < SK; k += 4) {
        float a1 = 0.f, a2 = 0.f, a3 = 0.f;
        for (int d = lane; d < Dm; d += 32) {
            float x = sm_dst[k][d];
            a1 += sm_rel[d] * x;
            a2 += x * x;
            a3 += sm_sr[d] * x;
        }
        a1 = warp_sum(a1); a2 = warp_sum(a2); a3 = warp_sum(a3);
        if (lane == 0) { sm_d1[k] = a1; sm_nr[k] = a2; sm_d2[k] = a3; }
    }
    __syncthreads();

    if (tid < 32) {
        int k = lane;
        bool valid = (k < SK) && (sm_id[k] >= 0);
        float omega = -INFINITY;
        if (valid) {
            long base = ((long)(b * Lq + l) * Sm + s) * SK + k;
            float cosv = fabsf(sm_d1[k]) / (sm_rn * sqrtf(sm_nr[k]) + 1e-8f);
            omega = 0.5f * wgt[base] * cosv + 0.5f * fabsf(sentic[base]);
        }
        float m = warp_max(omega);
        float e = valid ? __expf(omega - m) : 0.f;
        float ssum = warp_sum(e);
        float alpha1 = (ssum > 0.f) ? e / ssum : 0.f;
        float sv = valid ? alpha1 * sm_d2[k] : -INFINITY;
        float m2 = warp_max(sv);
        float e2 = valid ? __expf(sv - m2) : 0.f;
        float ssum2 = warp_sum(e2);
        float alpha2 = (ssum2 > 0.f) ? e2 / ssum2 : 0.f;
        if (k < SK) sm_coef[k] = alpha1 * alpha2;
    }
    __syncthreads();

    float psc = 0.f;
    for (int d = tid; d < Dm; d += 128) {
        float a = 0.f;
#pragma unroll
        for (int k = 0; k < SK; k++) a += sm_coef[k] * sm_dst[k][d];
        float nd = sm_src[d] + sm_rv[d] * a;
        g_nodes[nrow + d] = nd;
        psc += nd * sm_rel[d];
    }
    psc = warp_sum(psc);
    if (lane == 0) sm_red[w] = psc;
    __syncthreads();
    if (tid == 0) { g_score[l * 48 + n] = sm_red[0] + sm_red[1] + sm_red[2] + sm_red[3]; g_nmask[l * 48 + n] = 1; }
}

// ---------------- node-level attention -> sym ----------------
__global__ void k_sym()
{
    int l = blockIdx.x;
    int tid = threadIdx.x;  // 256
    __shared__ float att[48];
    __shared__ int sany;
    if (tid == 0) {
        float m = -INFINITY; int any = 0;
        for (int nn = 0; nn < 48; nn++)
            if (g_nmask[l * 48 + nn]) { any = 1; m = fmaxf(m, g_score[l * 48 + nn]); }
        float ssum = 0.f;
        for (int nn = 0; nn < 48; nn++) {
            float e = g_nmask[l * 48 + nn] ? __expf(g_score[l * 48 + nn] - m) : 0.f;
            att[nn] = e; ssum += e;
        }
        float inv = (ssum > 0.f) ? 1.f / ssum : 0.f;
        for (int nn = 0; nn < 48; nn++) att[nn] *= inv;
        sany = any;
    }
    __syncthreads();
    for (int d = tid; d < Dm; d += 256) {
        float a = 0.f;
#pragma unroll 8
        for (int nn = 0; nn < 48; nn++) a += att[nn] * g_nodes[(l * 48 + nn) * Dm + d];
        g_sym[l * Dm + d] = sany ? a : 0.f;
    }
}

// ---------------- final projection + log_softmax ----------------
__global__ void k_out(const float* __restrict__ Wout,
                      const float* __restrict__ bout, float* __restrict__ out)
{
    int l = blockIdx.x;
    int tid = threadIdx.x;  // 256
    int w = tid >> 5, lane = tid & 31;
    __shared__ float hs[Dm];
    __shared__ float logits[8];
    __shared__ float lse;
    for (int d = tid; d < Dm; d += 256) hs[d] = g_fuse[l * Dm + d];
    __syncthreads();
    if (w < Cm) {
        float a = 0.f;
        for (int d = lane; d < Dm; d += 32) a += hs[d] * Wout[d * Cm + w];
        a = warp_sum(a);
        if (lane == 0) logits[w] = a + bout[w];
    }
    __syncthreads();
    if (tid == 0) {
        float m = logits[0];
        for (int c = 1; c < Cm; c++) m = fmaxf(m, logits[c]);
        float ssum = 0.f;
        for (int c = 0; c < Cm; c++) ssum += __expf(logits[c] - m);
        lse = m + logf(ssum);
    }
    __syncthreads();
    if (tid < Cm) out[l * Cm + tid] = logits[tid] - lse;
}

// ---------------- launch ----------------
extern "C" void kernel_launch(void* const* d_in, const int* in_sizes, int n_in,
                              void* d_out, int out_size)
{
    (void)in_sizes; (void)n_in; (void)out_size;
    const float* utt   = (const float*)d_in[0];
    const int*   esrc  = (const int*)d_in[1];
    const int*   edst  = (const int*)d_in[2];
    const int*   etyp  = (const int*)d_in[3];
    const int*   csrc  = (const int*)d_in[4];
    const int*   cdst  = (const int*)d_in[5];
    const float* cwgt  = (const float*)d_in[6];
    const float* csen  = (const float*)d_in[7];
    const float* table = (const float*)d_in[8];
    const float* Wb    = (const float*)d_in[9];
    const float* comp  = (const float*)d_in[10];
    const float* Wself = (const float*)d_in[11];
    const float* brg   = (const float*)d_in[12];
    const float* Wq    = (const float*)d_in[13];
    const float* Wk    = (const float*)d_in[14];
    const float* Wv    = (const float*)d_in[15];
    const float* Wo    = (const float*)d_in[16];
    const float* rvec  = (const float*)d_in[17];
    const float* Wfuse = (const float*)d_in[18];
    const float* bfuse = (const float*)d_in[19];
    const float* Wout  = (const float*)d_in[20];
    const float* bout  = (const float*)d_in[21];

    // host-side symbol lookups (no stream ops, capture-safe); cached across calls
    static float* pLin = nullptr; static float* pCtx = nullptr; static float* pRel = nullptr;
    static float* pFuse = nullptr; static float* pPart = nullptr;
    if (!pLin) {
        cudaGetSymbolAddress((void**)&pLin,  g_Lin);
        cudaGetSymbolAddress((void**)&pCtx,  g_ctx);
        cudaGetSymbolAddress((void**)&pRel,  g_relatt);
        cudaGetSymbolAddress((void**)&pFuse, g_fuse);
        cudaGetSymbolAddress((void**)&pPart, g_part);
    }

    // 1) six fused linears: [P0|P1|Hself|Q|K|V] = utt @ [Wb0|Wb1|Wself|Wq|Wk|Wv]
    //    split-K=2 (kChunk 160): grid 29x4x2 = 232 blocks
    BPtrs six; six.p[0] = Wb; six.p[1] = Wb + 300 * 300; six.p[2] = Wself;
    six.p[3] = Wq; six.p[4] = Wk; six.p[5] = Wv;
    sgemm_splitk<0, 1><<<dim3(29, 4, 2), 256>>>(utt, six, pPart, Lq, 1800, Dm, 160);
    {
        int n4 = Lq * 1800 / 4;
        reduce_splitk<<<(n4 + 255) / 256, 256>>>((const float4*)pPart, (float4*)pLin,
                                                 n4, 2, nullptr, 0, 1800);
    }

    // 2) RGCN (deterministic per-dst edge scan)
    k_rgcn<<<Lq, 128>>>(brg, esrc, edst, etyp, comp);

    // 3) windowed attention context, then @ Wo with split-K=4 (80/80/80/60): 80 blocks
    k_relatt_ctx<<<Lq, 256>>>();
    BPtrs bo; bo.p[0] = Wo; bo.p[1] = bo.p[2] = bo.p[3] = bo.p[4] = bo.p[5] = nullptr;
    sgemm_splitk<0, 0><<<dim3(5, 4, 4), 256>>>(pCtx, bo, pPart, Lq, Dm, Dm, 80);
    {
        int n4 = Lq * Dm / 4;
        reduce_splitk<<<(n4 + 255) / 256, 256>>>((const float4*)pPart, (float4*)pRel,
                                                 n4, 4, nullptr, 0, Dm);
    }

    // 4) concept-graph nodes (the gather-heavy kernel)
    k_nodes<<<3 * Lq * Sm, 128>>>(table, csrc, cdst, cwgt, csen, rvec);

    // 5) node attention -> sym
    k_sym<<<Lq, 256>>>();

    // 6) fused [hidden|relatt|sym] @ Wfuse, split-K=6 (kChunk 160): 120 blocks
    //    reduction applies bias + relu
    BPtrs bf; bf.p[0] = Wfuse; bf.p[1] = bf.p[2] = bf.p[3] = bf.p[4] = bf.p[5] = nullptr;
    sgemm_splitk<1, 0><<<dim3(5, 4, 6), 256>>>(nullptr, bf, pPart, Lq, Dm, 900, 160);
    {
        int n4 = Lq * Dm / 4;
        reduce_splitk<<<(n4 + 255) / 256, 256>>>((const float4*)pPart, (float4*)pFuse,
                                                 n4, 6, bfuse, 1, Dm);
    }

    // 7) head + log_softmax
    k_out<<<Lq, 256>>>(Wout, bout, (float*)d_out);
}